// round 1
// baseline (speedup 1.0000x reference)
#include <cuda_runtime.h>
#include <cuda_bf16.h>
#include <cstdio>

#define NN   100000
#define EE   200000
#define GG   4096
#define HID  512
#define LAYERS 4
#define HEADS 8
#define BASES 8
#define NAGG 3
#define FH   64
#define COMBC (HEADS*BASES*NAGG)   // 192
#define DESC 200
#define CAT  (128 + DESC)          // 328
#define EPSBN 1e-5f

// ---------------- scratch (static device allocations; no cudaMalloc) ----------------
__device__ float    d_h    [(long)NN*HID];
__device__ float    d_t    [(long)NN*HID];
__device__ float    d_bases[(long)NN*HID];
__device__ float    d_comb [(long)NN*COMBC];
__device__ float    d_sum  [(long)NN*HID];
__device__ unsigned d_maxu [(long)NN*HID];
__device__ int      d_cnt  [NN];
__device__ float    d_part [256*2*HID];
__device__ float    d_scale[HID];
__device__ float    d_shift[HID];
__device__ float    d_pool [(long)GG*HID];
__device__ float    d_z1   [(long)GG*256];
__device__ float    d_z2   [(long)GG*128];
__device__ float    d_zc   [(long)GG*CAT];
__device__ float    d_z3   [(long)GG*128];

// ---------------- helpers ----------------
__device__ __forceinline__ unsigned encf(float f) {
    unsigned b = __float_as_uint(f);
    return (b & 0x80000000u) ? ~b : (b | 0x80000000u);
}
__device__ __forceinline__ float decf(unsigned u) {
    return (u & 0x80000000u) ? __uint_as_float(u ^ 0x80000000u) : __uint_as_float(~u);
}

// ---------------- lin1: out[n,c] = sum_k x[n,k]*W[k,c] (bias cancels in BN) ----------
__global__ void k_lin1(const float* __restrict__ x, const float* __restrict__ W,
                       float* __restrict__ out) {
    int n = blockIdx.x;
    __shared__ float xs[27];
    int tid = threadIdx.x;
    if (tid < 27) xs[tid] = x[n*27 + tid];
    __syncthreads();
    for (int c = tid; c < HID; c += blockDim.x) {
        float acc = 0.f;
        #pragma unroll
        for (int k = 0; k < 27; k++) acc += xs[k] * W[k*HID + c];
        out[(long)n*HID + c] = acc;
    }
}

// ---------------- generic tiled SGEMM: C = A[MxK] * B[KxN] (+bias) ------------------
#define BM 128
#define BN 128
#define BK 8
#define TM 8
#define TN 8
__global__ __launch_bounds__(256) void k_gemm(
    const float* __restrict__ A, const float* __restrict__ B,
    const float* __restrict__ bias, float* __restrict__ C,
    int M, int Nn, int K)
{
    __shared__ float As[BK][BM];
    __shared__ float Bs[BK][BN];
    int tid  = threadIdx.x;            // 256
    int row0 = blockIdx.y * BM;
    int col0 = blockIdx.x * BN;
    int tr = tid / 16, tc = tid % 16;
    float acc[TM][TN] = {};
    for (int kt = 0; kt < K; kt += BK) {
        #pragma unroll
        for (int i = 0; i < 4; i++) {
            int idx = tid + i*256;
            int m = idx >> 3, k = idx & 7;
            int gm = row0 + m, gk = kt + k;
            As[k][m] = (gm < M && gk < K) ? A[(long)gm*K + gk] : 0.f;
        }
        #pragma unroll
        for (int i = 0; i < 4; i++) {
            int idx = tid + i*256;
            int k = idx >> 7, n = idx & 127;
            int gk = kt + k, gn = col0 + n;
            Bs[k][n] = (gk < K && gn < Nn) ? B[(long)gk*Nn + gn] : 0.f;
        }
        __syncthreads();
        #pragma unroll
        for (int k = 0; k < BK; k++) {
            float a[TM], b[TN];
            #pragma unroll
            for (int i = 0; i < TM; i++) a[i] = As[k][tr*TM + i];
            #pragma unroll
            for (int j = 0; j < TN; j++) b[j] = Bs[k][tc*TN + j];
            #pragma unroll
            for (int i = 0; i < TM; i++)
                #pragma unroll
                for (int j = 0; j < TN; j++)
                    acc[i][j] += a[i] * b[j];
        }
        __syncthreads();
    }
    #pragma unroll
    for (int i = 0; i < TM; i++) {
        int gm = row0 + tr*TM + i;
        if (gm >= M) continue;
        #pragma unroll
        for (int j = 0; j < TN; j++) {
            int gn = col0 + tc*TN + j;
            if (gn < Nn) C[(long)gm*Nn + gn] = acc[i][j] + (bias ? bias[gn] : 0.f);
        }
    }
}

// ---------------- column stats (deterministic two pass) -----------------------------
__global__ void k_colstats_partial(const float* __restrict__ X, int M, int C, int chunks,
                                   float* __restrict__ part) {
    int c = threadIdx.x;            // blockDim.x == C
    int ch = blockIdx.x;
    int rpc = (M + chunks - 1) / chunks;
    int r0 = ch * rpc, r1 = min(M, r0 + rpc);
    float s = 0.f, ss = 0.f;
    for (int r = r0; r < r1; r++) {
        float v = X[(long)r*C + c];
        s += v; ss += v*v;
    }
    part[(long)ch*2*C + c]     = s;
    part[(long)ch*2*C + C + c] = ss;
}
__global__ void k_colstats_final(const float* __restrict__ part, int chunks, int C, int M,
                                 const float* __restrict__ g, const float* __restrict__ b,
                                 float* __restrict__ scale, float* __restrict__ shift) {
    int c = blockIdx.x * blockDim.x + threadIdx.x;
    if (c >= C) return;
    float s = 0.f, ss = 0.f;
    for (int ch = 0; ch < chunks; ch++) {
        s  += part[(long)ch*2*C + c];
        ss += part[(long)ch*2*C + C + c];
    }
    float mean = s / (float)M;
    float var  = ss / (float)M - mean*mean;
    float sc   = g[c] * rsqrtf(var + EPSBN);
    scale[c] = sc;
    shift[c] = b[c] - mean*sc;
}

// ---------------- bn+relu apply ------------------------------------------------------
__global__ void k_bn_apply(const float* __restrict__ X, const float* __restrict__ scale,
                           const float* __restrict__ shift, float* __restrict__ out,
                           long total, int C, int residual) {
    long i = blockIdx.x * (long)blockDim.x + threadIdx.x;
    if (i >= total) return;
    int c = (int)(i % C);
    float v = fmaxf(fmaf(X[i], scale[c], shift[c]), 0.f);
    if (residual) out[i] += v; else out[i] = v;
}

// ---------------- aggregation --------------------------------------------------------
__global__ void k_zero_agg() {
    long i = blockIdx.x * (long)blockDim.x + threadIdx.x;
    long nc = (long)NN * HID;
    if (i < nc) { d_sum[i] = 0.f; d_maxu[i] = 0u; }
    if (i < NN) d_cnt[i] = 0;
}
__global__ void k_scatter(const float* __restrict__ bases, const int* __restrict__ esrc,
                          const int* __restrict__ edst) {
    long idx = blockIdx.x * (long)blockDim.x + threadIdx.x;
    long tot = (long)(EE + NN) * 128;
    if (idx >= tot) return;
    int msg = (int)(idx >> 7);
    int q   = ((int)idx & 127) * 4;
    int s, d;
    if (msg < EE) { s = esrc[msg]; d = edst[msg]; }
    else          { s = msg - EE; d = s; }
    float4 v = *(const float4*)&bases[(long)s*HID + q];
    float* sp = &d_sum[(long)d*HID + q];
    atomicAdd(sp+0, v.x); atomicAdd(sp+1, v.y);
    atomicAdd(sp+2, v.z); atomicAdd(sp+3, v.w);
    unsigned* mp = &d_maxu[(long)d*HID + q];
    atomicMax(mp+0, encf(v.x)); atomicMax(mp+1, encf(v.y));
    atomicMax(mp+2, encf(v.z)); atomicMax(mp+3, encf(v.w));
    if (((int)idx & 127) == 0) atomicAdd(&d_cnt[d], 1);
}

// ---------------- per-node head combine (einsum) -------------------------------------
__global__ __launch_bounds__(512) void k_einsum(const float* __restrict__ comb,
                                                float* __restrict__ out) {
    int n = blockIdx.x;
    __shared__ float s_s[HID], s_m[HID], s_c[COMBC];
    __shared__ float s_invc;
    int tid = threadIdx.x; // 512
    s_s[tid] = d_sum[(long)n*HID + tid];
    s_m[tid] = decf(d_maxu[(long)n*HID + tid]);
    if (tid < COMBC) s_c[tid] = comb[(long)n*COMBC + tid];
    if (tid == 0)    s_invc = 1.f / (float)max(d_cnt[n], 1);
    __syncthreads();
    int h = tid >> 6, f = tid & 63;
    float invc = s_invc;
    float acc = 0.f;
    #pragma unroll
    for (int a = 0; a < NAGG; a++)
        #pragma unroll
        for (int b = 0; b < BASES; b++) {
            float w = s_c[h*(NAGG*BASES) + a*BASES + b];
            float v = (a == 0) ? s_s[b*FH + f]
                    : (a == 1) ? s_s[b*FH + f] * invc
                               : s_m[b*FH + f];
            acc += w * v;
        }
    out[(long)n*HID + tid] = acc;   // conv_bias cancels in the following BN
}

// ---------------- graph mean pool (batch is sorted) ----------------------------------
__global__ __launch_bounds__(512) void k_pool(const float* __restrict__ h,
                                              const int* __restrict__ batch) {
    int g = blockIdx.x;
    int tid = threadIdx.x; // 512
    int lo = 0, hi = NN;
    while (lo < hi) { int mid = (lo + hi) >> 1; if (batch[mid] < g) lo = mid + 1; else hi = mid; }
    int start = lo;
    hi = NN;
    while (lo < hi) { int mid = (lo + hi) >> 1; if (batch[mid] < g + 1) lo = mid + 1; else hi = mid; }
    int end = lo;
    float acc = 0.f;
    for (int i = start; i < end; i++) acc += h[(long)i*HID + tid];
    int c = end - start;
    d_pool[(long)g*HID + tid] = acc / (float)max(c, 1);
}

// ---------------- concat + final head ------------------------------------------------
__global__ void k_concat(const float* __restrict__ z, const float* __restrict__ desc) {
    int i = blockIdx.x * blockDim.x + threadIdx.x;
    if (i >= GG*CAT) return;
    int g = i / CAT, c = i % CAT;
    d_zc[i] = (c < 128) ? z[g*128 + c] : desc[g*DESC + (c - 128)];
}
__global__ void k_final(const float* __restrict__ z, const float* __restrict__ W,
                        const float* __restrict__ b, float* __restrict__ out) {
    int g = blockIdx.x * 8 + (threadIdx.x >> 5);
    int lane = threadIdx.x & 31;
    if (g >= GG) return;
    float acc = 0.f;
    #pragma unroll
    for (int k = lane; k < 128; k += 32) acc += z[g*128 + k] * W[k];
    #pragma unroll
    for (int o = 16; o; o >>= 1) acc += __shfl_down_sync(0xffffffffu, acc, o);
    if (lane == 0) out[g] = acc + b[0];
}

// ---------------- host orchestration --------------------------------------------------
static inline void* sym(const void* s) { void* p = nullptr; cudaGetSymbolAddress(&p, s); return p; }

extern "C" void kernel_launch(void* const* d_in, const int* in_sizes, int n_in,
                              void* d_out, int out_size) {
    const float* x       = (const float*)d_in[0];
    const int*   ei      = (const int*)  d_in[1];
    const int*   batch   = (const int*)  d_in[2];
    const float* desc    = (const float*)d_in[3];
    const float* lin1_W  = (const float*)d_in[4];
    // d_in[5] lin1_b: cancels in BN
    const float* norm1_g = (const float*)d_in[6];
    const float* norm1_b = (const float*)d_in[7];
    const float* Wb_all  = (const float*)d_in[8];
    const float* Wc_all  = (const float*)d_in[9];
    const float* bc_all  = (const float*)d_in[10];
    // d_in[11] conv_bias: cancels in BN
    const float* ng_all  = (const float*)d_in[12];
    const float* nb_all  = (const float*)d_in[13];
    const float* mlp_W1  = (const float*)d_in[14];
    const float* mlp_g1  = (const float*)d_in[15];
    const float* mlp_b1  = (const float*)d_in[16];
    const float* mlp_W2  = (const float*)d_in[17];
    const float* mlp_g2  = (const float*)d_in[18];
    const float* mlp_b2  = (const float*)d_in[19];
    const float* lin2_W  = (const float*)d_in[20];
    // d_in[21] lin2_b: cancels in BN
    const float* bn2_g   = (const float*)d_in[22];
    const float* bn2_b   = (const float*)d_in[23];
    const float* out_W   = (const float*)d_in[24];
    const float* out_b   = (const float*)d_in[25];
    float* out = (float*)d_out;

    const int* esrc = ei;
    const int* edst = ei + EE;

    float*    p_h     = (float*)   sym(d_h);
    float*    p_t     = (float*)   sym(d_t);
    float*    p_bases = (float*)   sym(d_bases);
    float*    p_comb  = (float*)   sym(d_comb);
    float*    p_part  = (float*)   sym(d_part);
    float*    p_scale = (float*)   sym(d_scale);
    float*    p_shift = (float*)   sym(d_shift);
    float*    p_pool  = (float*)   sym(d_pool);
    float*    p_z1    = (float*)   sym(d_z1);
    float*    p_z2    = (float*)   sym(d_z2);
    float*    p_zc    = (float*)   sym(d_zc);
    float*    p_z3    = (float*)   sym(d_z3);

    const long NH = (long)NN * HID;

    // ---- lin1 + BN + relu -> h ----
    k_lin1<<<NN, 256>>>(x, lin1_W, p_t);
    k_colstats_partial<<<256, HID>>>(p_t, NN, HID, 256, p_part);
    k_colstats_final<<<2, 256>>>(p_part, 256, HID, NN, norm1_g, norm1_b, p_scale, p_shift);
    k_bn_apply<<<(int)((NH + 255) / 256), 256>>>(p_t, p_scale, p_shift, p_h, NH, HID, 0);

    // ---- EGConv layers ----
    dim3 gemm_grid_b((HID + BN - 1) / BN, (NN + BM - 1) / BM);
    dim3 gemm_grid_c((COMBC + BN - 1) / BN, (NN + BM - 1) / BM);
    long scat_threads = (long)(EE + NN) * 128;
    int  scat_blocks  = (int)((scat_threads + 255) / 256);
    int  zero_blocks  = (int)((NH + 255) / 256);

    for (int l = 0; l < LAYERS; l++) {
        const float* Wb = Wb_all + (long)l * HID * HID;
        const float* Wc = Wc_all + (long)l * HID * COMBC;
        const float* bc = bc_all + (long)l * COMBC;
        const float* ng = ng_all + (long)l * HID;
        const float* nb = nb_all + (long)l * HID;

        k_gemm<<<gemm_grid_b, 256>>>(p_h, Wb, nullptr, p_bases, NN, HID, HID);
        k_gemm<<<gemm_grid_c, 256>>>(p_h, Wc, bc, p_comb, NN, COMBC, HID);
        k_zero_agg<<<zero_blocks, 256>>>();
        k_scatter<<<scat_blocks, 256>>>(p_bases, esrc, edst);
        k_einsum<<<NN, 512>>>(p_comb, p_t);
        k_colstats_partial<<<256, HID>>>(p_t, NN, HID, 256, p_part);
        k_colstats_final<<<2, 256>>>(p_part, 256, HID, NN, ng, nb, p_scale, p_shift);
        k_bn_apply<<<(int)((NH + 255) / 256), 256>>>(p_t, p_scale, p_shift, p_h, NH, HID, 1);
    }

    // ---- pool ----
    k_pool<<<GG, HID>>>(p_h, batch);

    // ---- MLP head ----
    dim3 g1((256 + BN - 1) / BN, (GG + BM - 1) / BM);
    k_gemm<<<g1, 256>>>(p_pool, mlp_W1, nullptr, p_z1, GG, 256, HID);
    k_colstats_partial<<<64, 256>>>(p_z1, GG, 256, 64, p_part);
    k_colstats_final<<<1, 256>>>(p_part, 64, 256, GG, mlp_g1, mlp_b1, p_scale, p_shift);
    k_bn_apply<<<(int)(((long)GG*256 + 255) / 256), 256>>>(p_z1, p_scale, p_shift, p_z1, (long)GG*256, 256, 0);

    dim3 g2((128 + BN - 1) / BN, (GG + BM - 1) / BM);
    k_gemm<<<g2, 256>>>(p_z1, mlp_W2, nullptr, p_z2, GG, 128, 256);
    k_colstats_partial<<<64, 128>>>(p_z2, GG, 128, 64, p_part);
    k_colstats_final<<<1, 128>>>(p_part, 64, 128, GG, mlp_g2, mlp_b2, p_scale, p_shift);
    k_bn_apply<<<(int)(((long)GG*128 + 255) / 256), 256>>>(p_z2, p_scale, p_shift, p_z2, (long)GG*128, 128, 0);

    k_concat<<<(GG*CAT + 255) / 256, 256>>>(p_z2, desc);

    dim3 g3((128 + BN - 1) / BN, (GG + BM - 1) / BM);
    k_gemm<<<g3, 256>>>(p_zc, lin2_W, nullptr, p_z3, GG, 128, CAT);
    k_colstats_partial<<<64, 128>>>(p_z3, GG, 128, 64, p_part);
    k_colstats_final<<<1, 128>>>(p_part, 64, 128, GG, bn2_g, bn2_b, p_scale, p_shift);
    k_bn_apply<<<(int)(((long)GG*128 + 255) / 256), 256>>>(p_z3, p_scale, p_shift, p_z3, (long)GG*128, 128, 0);

    k_final<<<GG / 8, 256>>>(p_z3, out_W, out_b, out);
}

// round 2
// speedup vs baseline: 4.5479x; 4.5479x over previous
#include <cuda_runtime.h>
#include <cstdint>

#define NN   100000
#define EE   200000
#define GG   4096
#define HID  512
#define LAYERS 4
#define HEADS 8
#define BASES 8
#define NAGG 3
#define FH   64
#define COMBC (HEADS*BASES*NAGG)   // 192
#define DESC 200
#define CAT  (128 + DESC)          // 328
#define EPSBN 1e-5f

// ---------------- scratch (static device allocations; no cudaMalloc) ----------------
__device__ float d_h    [(long)NN*HID];
__device__ float d_t    [(long)NN*HID];
__device__ float d_bases[(long)NN*HID];
__device__ float d_comb [(long)NN*COMBC];
__device__ float d_part [256*2*HID];
__device__ float d_scale[HID];
__device__ float d_shift[HID];
__device__ float d_pool [(long)GG*HID];
__device__ float d_z1   [(long)GG*256];
__device__ float d_z2   [(long)GG*128];
__device__ float d_zc   [(long)GG*CAT];
__device__ float d_z3   [(long)GG*128];
// CSR
__device__ int d_deg [NN];
__device__ int d_off [NN+1];
__device__ int d_cur [NN];
__device__ int d_csrc[EE];
__device__ int d_bsum[256];

// ---------------- lin1 -----------------------------------------------------------
__global__ void k_lin1(const float* __restrict__ x, const float* __restrict__ W,
                       float* __restrict__ out) {
    int n = blockIdx.x;
    __shared__ float xs[27];
    int tid = threadIdx.x;
    if (tid < 27) xs[tid] = x[n*27 + tid];
    __syncthreads();
    for (int c = tid; c < HID; c += blockDim.x) {
        float acc = 0.f;
        #pragma unroll
        for (int k = 0; k < 27; k++) acc += xs[k] * W[k*HID + c];
        out[(long)n*HID + c] = acc;
    }
}

// ---------------- fp32 tiled SGEMM (kept for small head GEMMs) --------------------
#define BM 128
#define BN 128
#define BK 8
#define TM 8
#define TN 8
__global__ __launch_bounds__(256) void k_gemm(
    const float* __restrict__ A, const float* __restrict__ B,
    const float* __restrict__ bias, float* __restrict__ C,
    int M, int Nn, int K)
{
    __shared__ float As[BK][BM];
    __shared__ float Bs[BK][BN];
    int tid  = threadIdx.x;
    int row0 = blockIdx.y * BM;
    int col0 = blockIdx.x * BN;
    int tr = tid / 16, tc = tid % 16;
    float acc[TM][TN] = {};
    for (int kt = 0; kt < K; kt += BK) {
        #pragma unroll
        for (int i = 0; i < 4; i++) {
            int idx = tid + i*256;
            int m = idx >> 3, k = idx & 7;
            int gm = row0 + m, gk = kt + k;
            As[k][m] = (gm < M && gk < K) ? A[(long)gm*K + gk] : 0.f;
        }
        #pragma unroll
        for (int i = 0; i < 4; i++) {
            int idx = tid + i*256;
            int k = idx >> 7, n = idx & 127;
            int gk = kt + k, gn = col0 + n;
            Bs[k][n] = (gk < K && gn < Nn) ? B[(long)gk*Nn + gn] : 0.f;
        }
        __syncthreads();
        #pragma unroll
        for (int k = 0; k < BK; k++) {
            float a[TM], b[TN];
            #pragma unroll
            for (int i = 0; i < TM; i++) a[i] = As[k][tr*TM + i];
            #pragma unroll
            for (int j = 0; j < TN; j++) b[j] = Bs[k][tc*TN + j];
            #pragma unroll
            for (int i = 0; i < TM; i++)
                #pragma unroll
                for (int j = 0; j < TN; j++)
                    acc[i][j] += a[i] * b[j];
        }
        __syncthreads();
    }
    #pragma unroll
    for (int i = 0; i < TM; i++) {
        int gm = row0 + tr*TM + i;
        if (gm >= M) continue;
        #pragma unroll
        for (int j = 0; j < TN; j++) {
            int gn = col0 + tc*TN + j;
            if (gn < Nn) C[(long)gm*Nn + gn] = acc[i][j] + (bias ? bias[gn] : 0.f);
        }
    }
}

// ---------------- tf32 tensor-core GEMM: C = A[MxK] * B[KxN] (+bias) --------------
// 128x128 CTA tile, BK=16, 8 warps (2x4), warp tile 64x32, mma.m16n8k8.tf32,
// cp.async double-buffered.
__device__ __forceinline__ uint32_t f2tf32(float f) {
    uint32_t r; asm("cvt.rna.tf32.f32 %0, %1;" : "=r"(r) : "f"(f)); return r;
}
__device__ __forceinline__ void mma_tf32(float* c, const uint32_t* a, const uint32_t* b) {
    asm volatile("mma.sync.aligned.m16n8k8.row.col.f32.tf32.tf32.f32 "
        "{%0,%1,%2,%3},{%4,%5,%6,%7},{%8,%9},{%0,%1,%2,%3};"
        : "+f"(c[0]), "+f"(c[1]), "+f"(c[2]), "+f"(c[3])
        : "r"(a[0]), "r"(a[1]), "r"(a[2]), "r"(a[3]), "r"(b[0]), "r"(b[1]));
}
__device__ __forceinline__ void cp_async16(void* smem, const void* gmem, bool pred) {
    unsigned sa = (unsigned)__cvta_generic_to_shared(smem);
    int sz = pred ? 16 : 0;
    asm volatile("cp.async.cg.shared.global [%0], [%1], 16, %2;"
                 :: "r"(sa), "l"(gmem), "r"(sz));
}

#define GBK 16
__global__ __launch_bounds__(256) void k_gemm_tf32(
    const float* __restrict__ A, const float* __restrict__ B,
    const float* __restrict__ bias, float* __restrict__ C,
    int M, int Nn, int K)
{
    __shared__ float As[2][128][20];   // [m][k], pad 4 -> conflict free frags
    __shared__ float Bs[2][GBK][136];  // [k][n], pad 8 -> conflict free frags

    int tid = threadIdx.x;
    int row0 = blockIdx.y * 128;
    int col0 = blockIdx.x * 128;
    int lane = tid & 31, warp = tid >> 5;
    int mbase = (warp & 1) * 64;
    int nbase = (warp >> 1) * 32;
    int qi = lane >> 2;     // 0..7
    int qk = lane & 3;      // 0..3

    // global-load indices
    int ar = tid >> 2;           // 0..63  (A rows ar, ar+64)
    int ac = (tid & 3) * 4;      // 0..12
    int br = tid >> 5;           // 0..7   (B rows br, br+8)
    int bc = (tid & 31) * 4;     // 0..124

    float acc[4][4][4] = {};
    int KT = K / GBK;

    // prologue: stage 0
    {
        const float* pa0 = A + (long)(row0 + ar) * K + ac;
        const float* pa1 = A + (long)(row0 + ar + 64) * K + ac;
        bool p0 = (row0 + ar) < M, p1 = (row0 + ar + 64) < M;
        cp_async16(&As[0][ar][ac],      p0 ? pa0 : A, p0);
        cp_async16(&As[0][ar + 64][ac], p1 ? pa1 : A, p1);
        bool pb = (col0 + bc) < Nn;
        const float* pb0 = B + (long)br * Nn + col0 + bc;
        const float* pb1 = B + (long)(br + 8) * Nn + col0 + bc;
        cp_async16(&Bs[0][br][bc],     pb ? pb0 : B, pb);
        cp_async16(&Bs[0][br + 8][bc], pb ? pb1 : B, pb);
        asm volatile("cp.async.commit_group;");
    }

    for (int kt = 0; kt < KT; kt++) {
        int cur = kt & 1;
        if (kt + 1 < KT) {
            int nxt = cur ^ 1;
            int kg = (kt + 1) * GBK;
            const float* pa0 = A + (long)(row0 + ar) * K + kg + ac;
            const float* pa1 = A + (long)(row0 + ar + 64) * K + kg + ac;
            bool p0 = (row0 + ar) < M, p1 = (row0 + ar + 64) < M;
            cp_async16(&As[nxt][ar][ac],      p0 ? pa0 : A, p0);
            cp_async16(&As[nxt][ar + 64][ac], p1 ? pa1 : A, p1);
            bool pb = (col0 + bc) < Nn;
            const float* pb0 = B + (long)(kg + br) * Nn + col0 + bc;
            const float* pb1 = B + (long)(kg + br + 8) * Nn + col0 + bc;
            cp_async16(&Bs[nxt][br][bc],     pb ? pb0 : B, pb);
            cp_async16(&Bs[nxt][br + 8][bc], pb ? pb1 : B, pb);
            asm volatile("cp.async.commit_group;");
            asm volatile("cp.async.wait_group 1;");
        } else {
            asm volatile("cp.async.wait_group 0;");
        }
        __syncthreads();

        #pragma unroll
        for (int ks = 0; ks < 2; ks++) {
            uint32_t afr[4][4], bfr[4][2];
            #pragma unroll
            for (int mt = 0; mt < 4; mt++) {
                int r = mbase + mt*16 + qi;
                int k = ks*8 + qk;
                afr[mt][0] = f2tf32(As[cur][r    ][k    ]);
                afr[mt][1] = f2tf32(As[cur][r + 8][k    ]);
                afr[mt][2] = f2tf32(As[cur][r    ][k + 4]);
                afr[mt][3] = f2tf32(As[cur][r + 8][k + 4]);
            }
            #pragma unroll
            for (int nt = 0; nt < 4; nt++) {
                int cn = nbase + nt*8 + qi;
                int k = ks*8 + qk;
                bfr[nt][0] = f2tf32(Bs[cur][k    ][cn]);
                bfr[nt][1] = f2tf32(Bs[cur][k + 4][cn]);
            }
            #pragma unroll
            for (int mt = 0; mt < 4; mt++)
                #pragma unroll
                for (int nt = 0; nt < 4; nt++)
                    mma_tf32(acc[mt][nt], afr[mt], bfr[nt]);
        }
        __syncthreads();
    }

    // epilogue
    #pragma unroll
    for (int mt = 0; mt < 4; mt++) {
        int r0 = row0 + mbase + mt*16 + qi;
        #pragma unroll
        for (int nt = 0; nt < 4; nt++) {
            int cn = col0 + nbase + nt*8 + qk*2;
            if (cn < Nn) {
                float b0 = bias ? bias[cn] : 0.f;
                float b1 = bias ? bias[cn + 1] : 0.f;
                if (r0 < M) {
                    C[(long)r0*Nn + cn]     = acc[mt][nt][0] + b0;
                    C[(long)r0*Nn + cn + 1] = acc[mt][nt][1] + b1;
                }
                if (r0 + 8 < M) {
                    C[(long)(r0+8)*Nn + cn]     = acc[mt][nt][2] + b0;
                    C[(long)(r0+8)*Nn + cn + 1] = acc[mt][nt][3] + b1;
                }
            }
        }
    }
}

// ---------------- column stats (deterministic two pass) ---------------------------
__global__ void k_colstats_partial(const float* __restrict__ X, int M, int C, int chunks,
                                   float* __restrict__ part) {
    int c = threadIdx.x;
    int ch = blockIdx.x;
    int rpc = (M + chunks - 1) / chunks;
    int r0 = ch * rpc, r1 = min(M, r0 + rpc);
    float s = 0.f, ss = 0.f;
    for (int r = r0; r < r1; r++) {
        float v = X[(long)r*C + c];
        s += v; ss += v*v;
    }
    part[(long)ch*2*C + c]     = s;
    part[(long)ch*2*C + C + c] = ss;
}
__global__ void k_colstats_final(const float* __restrict__ part, int chunks, int C, int M,
                                 const float* __restrict__ g, const float* __restrict__ b,
                                 float* __restrict__ scale, float* __restrict__ shift) {
    int c = blockIdx.x * blockDim.x + threadIdx.x;
    if (c >= C) return;
    float s = 0.f, ss = 0.f;
    for (int ch = 0; ch < chunks; ch++) {
        s  += part[(long)ch*2*C + c];
        ss += part[(long)ch*2*C + C + c];
    }
    float mean = s / (float)M;
    float var  = ss / (float)M - mean*mean;
    float sc   = g[c] * rsqrtf(var + EPSBN);
    scale[c] = sc;
    shift[c] = b[c] - mean*sc;
}

// ---------------- bn+relu apply, float4 --------------------------------------------
__global__ void k_bn4(const float4* __restrict__ X, const float* __restrict__ scale,
                      const float* __restrict__ shift, float4* __restrict__ out,
                      int total4, int c4mask, int residual) {
    int i = blockIdx.x * blockDim.x + threadIdx.x;
    if (i >= total4) return;
    int c = (i & c4mask) * 4;
    float4 v = X[i];
    float4 r;
    r.x = fmaxf(fmaf(v.x, scale[c+0], shift[c+0]), 0.f);
    r.y = fmaxf(fmaf(v.y, scale[c+1], shift[c+1]), 0.f);
    r.z = fmaxf(fmaf(v.z, scale[c+2], shift[c+2]), 0.f);
    r.w = fmaxf(fmaf(v.w, scale[c+3], shift[c+3]), 0.f);
    if (residual) {
        float4 h = out[i];
        r.x += h.x; r.y += h.y; r.z += h.z; r.w += h.w;
    }
    out[i] = r;
}

// ---------------- CSR build --------------------------------------------------------
__global__ void k_csr_zero() {
    int i = blockIdx.x * blockDim.x + threadIdx.x;
    if (i < NN) { d_deg[i] = 0; d_cur[i] = 0; }
}
__global__ void k_csr_count(const int* __restrict__ edst) {
    int e = blockIdx.x * blockDim.x + threadIdx.x;
    if (e < EE) atomicAdd(&d_deg[edst[e]], 1);
}
#define SCB 200
#define SCCHUNK 500
__global__ void k_scan_part() {
    int b = blockIdx.x, t = threadIdx.x;
    int beg = b * SCCHUNK, endn = min(beg + SCCHUNK, NN);
    int s = 0;
    for (int i = beg + t; i < endn; i += 128) s += d_deg[i];
    __shared__ int sh[128];
    sh[t] = s; __syncthreads();
    for (int o = 64; o; o >>= 1) { if (t < o) sh[t] += sh[t+o]; __syncthreads(); }
    if (!t) d_bsum[b] = sh[0];
}
__global__ void k_scan_mid() {
    int run = 0;
    for (int i = 0; i < SCB; i++) { int v = d_bsum[i]; d_bsum[i] = run; run += v; }
}
__global__ void k_scan_write() {
    int b = blockIdx.x;
    int run = d_bsum[b];
    int beg = b * SCCHUNK, endn = min(beg + SCCHUNK, NN);
    for (int i = beg; i < endn; i++) { d_off[i] = run; run += d_deg[i]; }
    if (b == SCB - 1) d_off[NN] = run;
}
__global__ void k_csr_fill(const int* __restrict__ esrc, const int* __restrict__ edst) {
    int e = blockIdx.x * blockDim.x + threadIdx.x;
    if (e >= EE) return;
    int d = edst[e];
    int p = d_off[d] + atomicAdd(&d_cur[d], 1);
    d_csrc[p] = esrc[e];
}

// ---------------- fused aggregation + head-combine einsum --------------------------
__global__ __launch_bounds__(128) void k_agg(const float* __restrict__ bases,
                                             const float* __restrict__ comb,
                                             float* __restrict__ out) {
    int n = blockIdx.x;
    int tid = threadIdx.x;       // 128, each owns 4 contiguous cols
    __shared__ float s_s[HID], s_m[HID], s_c[COMBC];
    __shared__ int   s_idx[128];

    int q = tid * 4;
    const float4* brow = (const float4*)&bases[(long)n*HID];
    float4 sv = brow[tid];       // self message
    float4 mv = sv;

    int beg = d_off[n], endp = d_off[n+1];
    for (int base = beg; base < endp; base += 128) {
        int m = min(128, endp - base);
        if (tid < m) s_idx[tid] = d_csrc[base + tid];
        __syncthreads();
        for (int j = 0; j < m; j++) {
            const float4 v = ((const float4*)&bases[(long)s_idx[j]*HID])[tid];
            sv.x += v.x; sv.y += v.y; sv.z += v.z; sv.w += v.w;
            mv.x = fmaxf(mv.x, v.x); mv.y = fmaxf(mv.y, v.y);
            mv.z = fmaxf(mv.z, v.z); mv.w = fmaxf(mv.w, v.w);
        }
        __syncthreads();
    }

    ((float4*)s_s)[tid] = sv;
    ((float4*)s_m)[tid] = mv;
    if (tid < COMBC/4) ((float4*)s_c)[tid] = ((const float4*)&comb[(long)n*COMBC])[tid];
    __syncthreads();

    float invc = 1.f / (float)(endp - beg + 1);
    int h = q >> 6;                     // same head for all 4 cols
    const float* w = &s_c[h * (NAGG*BASES)];
    float o[4] = {0.f, 0.f, 0.f, 0.f};
    #pragma unroll
    for (int b = 0; b < BASES; b++) {
        float ws = w[b] ;               // sum weight
        float wm = w[8 + b];            // mean weight
        float wx = w[16 + b];           // max weight
        #pragma unroll
        for (int j = 0; j < 4; j++) {
            int f = (q + j) & 63;
            float s = s_s[b*FH + f];
            float x = s_m[b*FH + f];
            o[j] += ws * s + wm * s * invc + wx * x;
        }
    }
    float4 r; r.x = o[0]; r.y = o[1]; r.z = o[2]; r.w = o[3];
    ((float4*)&out[(long)n*HID])[tid] = r;
}

// ---------------- graph mean pool (batch sorted) -----------------------------------
__global__ __launch_bounds__(512) void k_pool(const float* __restrict__ h,
                                              const int* __restrict__ batch) {
    int g = blockIdx.x;
    int tid = threadIdx.x;
    int lo = 0, hi = NN;
    while (lo < hi) { int mid = (lo + hi) >> 1; if (batch[mid] < g) lo = mid + 1; else hi = mid; }
    int start = lo;
    hi = NN;
    while (lo < hi) { int mid = (lo + hi) >> 1; if (batch[mid] < g + 1) lo = mid + 1; else hi = mid; }
    int end = lo;
    float acc = 0.f;
    for (int i = start; i < end; i++) acc += h[(long)i*HID + tid];
    int c = end - start;
    d_pool[(long)g*HID + tid] = acc / (float)max(c, 1);
}

// ---------------- concat + final head ----------------------------------------------
__global__ void k_concat(const float* __restrict__ z, const float* __restrict__ desc) {
    int i = blockIdx.x * blockDim.x + threadIdx.x;
    if (i >= GG*CAT) return;
    int g = i / CAT, c = i % CAT;
    d_zc[i] = (c < 128) ? z[g*128 + c] : desc[g*DESC + (c - 128)];
}
__global__ void k_final(const float* __restrict__ z, const float* __restrict__ W,
                        const float* __restrict__ b, float* __restrict__ out) {
    int g = blockIdx.x * 8 + (threadIdx.x >> 5);
    int lane = threadIdx.x & 31;
    if (g >= GG) return;
    float acc = 0.f;
    #pragma unroll
    for (int k = lane; k < 128; k += 32) acc += z[g*128 + k] * W[k];
    #pragma unroll
    for (int o = 16; o; o >>= 1) acc += __shfl_down_sync(0xffffffffu, acc, o);
    if (lane == 0) out[g] = acc + b[0];
}

// ---------------- host orchestration ------------------------------------------------
static inline void* sym(const void* s) { void* p = nullptr; cudaGetSymbolAddress(&p, s); return p; }

extern "C" void kernel_launch(void* const* d_in, const int* in_sizes, int n_in,
                              void* d_out, int out_size) {
    const float* x       = (const float*)d_in[0];
    const int*   ei      = (const int*)  d_in[1];
    const int*   batch   = (const int*)  d_in[2];
    const float* desc    = (const float*)d_in[3];
    const float* lin1_W  = (const float*)d_in[4];
    const float* norm1_g = (const float*)d_in[6];
    const float* norm1_b = (const float*)d_in[7];
    const float* Wb_all  = (const float*)d_in[8];
    const float* Wc_all  = (const float*)d_in[9];
    const float* bc_all  = (const float*)d_in[10];
    const float* ng_all  = (const float*)d_in[12];
    const float* nb_all  = (const float*)d_in[13];
    const float* mlp_W1  = (const float*)d_in[14];
    const float* mlp_g1  = (const float*)d_in[15];
    const float* mlp_b1  = (const float*)d_in[16];
    const float* mlp_W2  = (const float*)d_in[17];
    const float* mlp_g2  = (const float*)d_in[18];
    const float* mlp_b2  = (const float*)d_in[19];
    const float* lin2_W  = (const float*)d_in[20];
    const float* bn2_g   = (const float*)d_in[22];
    const float* bn2_b   = (const float*)d_in[23];
    const float* out_W   = (const float*)d_in[24];
    const float* out_b   = (const float*)d_in[25];
    float* out = (float*)d_out;

    const int* esrc = ei;
    const int* edst = ei + EE;

    float* p_h     = (float*)sym(d_h);
    float* p_t     = (float*)sym(d_t);
    float* p_bases = (float*)sym(d_bases);
    float* p_comb  = (float*)sym(d_comb);
    float* p_part  = (float*)sym(d_part);
    float* p_scale = (float*)sym(d_scale);
    float* p_shift = (float*)sym(d_shift);
    float* p_pool  = (float*)sym(d_pool);
    float* p_z1    = (float*)sym(d_z1);
    float* p_z2    = (float*)sym(d_z2);
    float* p_zc    = (float*)sym(d_zc);
    float* p_z3    = (float*)sym(d_z3);

    const int NH4 = NN * (HID/4);   // 12.8M float4

    // ---- CSR build (edges constant; part of the captured graph) ----
    k_csr_zero <<<(NN + 255)/256, 256>>>();
    k_csr_count<<<(EE + 255)/256, 256>>>(edst);
    k_scan_part<<<SCB, 128>>>();
    k_scan_mid <<<1, 1>>>();
    k_scan_write<<<SCB, 1>>>();
    k_csr_fill <<<(EE + 255)/256, 256>>>(esrc, edst);

    // ---- lin1 + BN + relu -> h ----
    k_lin1<<<NN, 256>>>(x, lin1_W, p_t);
    k_colstats_partial<<<256, HID>>>(p_t, NN, HID, 256, p_part);
    k_colstats_final<<<2, 256>>>(p_part, 256, HID, NN, norm1_g, norm1_b, p_scale, p_shift);
    k_bn4<<<(NH4 + 255)/256, 256>>>((const float4*)p_t, p_scale, p_shift,
                                    (float4*)p_h, NH4, (HID/4)-1, 0);

    // ---- EGConv layers ----
    dim3 grid_b(HID/128, (NN + 127)/128);
    dim3 grid_c((COMBC + 127)/128, (NN + 127)/128);

    for (int l = 0; l < LAYERS; l++) {
        const float* Wb = Wb_all + (long)l * HID * HID;
        const float* Wc = Wc_all + (long)l * HID * COMBC;
        const float* bc = bc_all + (long)l * COMBC;
        const float* ng = ng_all + (long)l * HID;
        const float* nb = nb_all + (long)l * HID;

        k_gemm_tf32<<<grid_b, 256>>>(p_h, Wb, nullptr, p_bases, NN, HID, HID);
        k_gemm_tf32<<<grid_c, 256>>>(p_h, Wc, bc, p_comb, NN, COMBC, HID);
        k_agg<<<NN, 128>>>(p_bases, p_comb, p_t);
        k_colstats_partial<<<256, HID>>>(p_t, NN, HID, 256, p_part);
        k_colstats_final<<<2, 256>>>(p_part, 256, HID, NN, ng, nb, p_scale, p_shift);
        k_bn4<<<(NH4 + 255)/256, 256>>>((const float4*)p_t, p_scale, p_shift,
                                        (float4*)p_h, NH4, (HID/4)-1, 1);
    }

    // ---- pool ----
    k_pool<<<GG, HID>>>(p_h, batch);

    // ---- MLP head (fp32 GEMMs, small) ----
    dim3 g1((256 + BN - 1)/BN, (GG + BM - 1)/BM);
    k_gemm<<<g1, 256>>>(p_pool, mlp_W1, nullptr, p_z1, GG, 256, HID);
    k_colstats_partial<<<64, 256>>>(p_z1, GG, 256, 64, p_part);
    k_colstats_final<<<1, 256>>>(p_part, 64, 256, GG, mlp_g1, mlp_b1, p_scale, p_shift);
    k_bn4<<<(GG*64 + 255)/256, 256>>>((const float4*)p_z1, p_scale, p_shift,
                                      (float4*)p_z1, GG*64, 63, 0);

    dim3 g2((128 + BN - 1)/BN, (GG + BM - 1)/BM);
    k_gemm<<<g2, 256>>>(p_z1, mlp_W2, nullptr, p_z2, GG, 128, 256);
    k_colstats_partial<<<64, 128>>>(p_z2, GG, 128, 64, p_part);
    k_colstats_final<<<1, 128>>>(p_part, 64, 128, GG, mlp_g2, mlp_b2, p_scale, p_shift);
    k_bn4<<<(GG*32 + 255)/256, 256>>>((const float4*)p_z2, p_scale, p_shift,
                                      (float4*)p_z2, GG*32, 31, 0);

    k_concat<<<(GG*CAT + 255)/256, 256>>>(p_z2, desc);

    dim3 g3((128 + BN - 1)/BN, (GG + BM - 1)/BM);
    k_gemm<<<g3, 256>>>(p_zc, lin2_W, nullptr, p_z3, GG, 128, CAT);
    k_colstats_partial<<<64, 128>>>(p_z3, GG, 128, 64, p_part);
    k_colstats_final<<<1, 128>>>(p_part, 64, 128, GG, bn2_g, bn2_b, p_scale, p_shift);
    k_bn4<<<(GG*32 + 255)/256, 256>>>((const float4*)p_z3, p_scale, p_shift,
                                      (float4*)p_z3, GG*32, 31, 0);

    k_final<<<GG/8, 256>>>(p_z3, out_W, out_b, out);
}

// round 3
// speedup vs baseline: 5.9387x; 1.3058x over previous
#include <cuda_runtime.h>
#include <cuda_fp16.h>
#include <cstdint>

#define NN   100000
#define EE   200000
#define GG   4096
#define HID  512
#define LAYERS 4
#define HEADS 8
#define BASES 8
#define NAGG 3
#define FH   64
#define COMBC 192
#define COMBP 256
#define DESC 200
#define CAT  (128 + DESC)          // 328
#define EPSBN 1e-5f

// ---------------- scratch (static device allocations; no cudaMalloc) ----------------
__device__ float  d_h    [(long)NN*HID];
__device__ __half d_hh   [(long)NN*HID];
__device__ float  d_t    [(long)NN*HID];
__device__ float  d_bases[(long)NN*HID];
__device__ float  d_comb [(long)NN*COMBP];
__device__ float  d_part [256*2*HID];
__device__ float  d_scale[HID];
__device__ float  d_shift[HID];
__device__ float  d_pool [(long)GG*HID];
__device__ float  d_z1   [(long)GG*256];
__device__ float  d_z2   [(long)GG*128];
__device__ float  d_zc   [(long)GG*CAT];
__device__ float  d_z3   [(long)GG*128];
__device__ __half d_wb16 [(long)LAYERS*HID*HID];
__device__ __half d_wc16 [(long)LAYERS*HID*COMBP];
__device__ float  d_bcp  [LAYERS*COMBP];
// CSR
__device__ int d_deg [NN];
__device__ int d_off [NN+1];
__device__ int d_cur [NN];
__device__ int d_csrc[EE];
__device__ int d_bsum[256];

// ---------------- lin1 -----------------------------------------------------------
__global__ void k_lin1(const float* __restrict__ x, const float* __restrict__ W,
                       float* __restrict__ out) {
    int n = blockIdx.x;
    __shared__ float xs[27];
    int tid = threadIdx.x;
    if (tid < 27) xs[tid] = x[n*27 + tid];
    __syncthreads();
    for (int c = tid; c < HID; c += blockDim.x) {
        float acc = 0.f;
        #pragma unroll
        for (int k = 0; k < 27; k++) acc += xs[k] * W[k*HID + c];
        out[(long)n*HID + c] = acc;
    }
}

// ---------------- fp32 tiled SGEMM (small head GEMMs) ------------------------------
#define BM 128
#define BN 128
#define BK 8
#define TM 8
#define TN 8
__global__ __launch_bounds__(256) void k_gemm(
    const float* __restrict__ A, const float* __restrict__ B,
    const float* __restrict__ bias, float* __restrict__ C,
    int M, int Nn, int K)
{
    __shared__ float As[BK][BM];
    __shared__ float Bs[BK][BN];
    int tid  = threadIdx.x;
    int row0 = blockIdx.y * BM;
    int col0 = blockIdx.x * BN;
    int tr = tid / 16, tc = tid % 16;
    float acc[TM][TN] = {};
    for (int kt = 0; kt < K; kt += BK) {
        #pragma unroll
        for (int i = 0; i < 4; i++) {
            int idx = tid + i*256;
            int m = idx >> 3, k = idx & 7;
            int gm = row0 + m, gk = kt + k;
            As[k][m] = (gm < M && gk < K) ? A[(long)gm*K + gk] : 0.f;
        }
        #pragma unroll
        for (int i = 0; i < 4; i++) {
            int idx = tid + i*256;
            int k = idx >> 7, n = idx & 127;
            int gk = kt + k, gn = col0 + n;
            Bs[k][n] = (gk < K && gn < Nn) ? B[(long)gk*Nn + gn] : 0.f;
        }
        __syncthreads();
        #pragma unroll
        for (int k = 0; k < BK; k++) {
            float a[TM], b[TN];
            #pragma unroll
            for (int i = 0; i < TM; i++) a[i] = As[k][tr*TM + i];
            #pragma unroll
            for (int j = 0; j < TN; j++) b[j] = Bs[k][tc*TN + j];
            #pragma unroll
            for (int i = 0; i < TM; i++)
                #pragma unroll
                for (int j = 0; j < TN; j++)
                    acc[i][j] += a[i] * b[j];
        }
        __syncthreads();
    }
    #pragma unroll
    for (int i = 0; i < TM; i++) {
        int gm = row0 + tr*TM + i;
        if (gm >= M) continue;
        #pragma unroll
        for (int j = 0; j < TN; j++) {
            int gn = col0 + tc*TN + j;
            if (gn < Nn) C[(long)gm*Nn + gn] = acc[i][j] + (bias ? bias[gn] : 0.f);
        }
    }
}

// ---------------- fp16 tensor-core GEMM ---------------------------------------------
// C[MxN] = A[MxK](f16) * B[KxN](f16) + bias. Requires K%32==0, N%128==0 and B fully
// padded (no N guards). 128x128 CTA tile, BK=32, 8 warps (2x4), warp tile 64x32,
// mma.m16n8k16 via ldmatrix, double-buffered cp.async.
__device__ __forceinline__ void cp_async16(void* smem, const void* gmem, bool pred) {
    unsigned sa = (unsigned)__cvta_generic_to_shared(smem);
    int sz = pred ? 16 : 0;
    asm volatile("cp.async.cg.shared.global [%0], [%1], 16, %2;"
                 :: "r"(sa), "l"(gmem), "r"(sz));
}
__device__ __forceinline__ void ldsm_x4(uint32_t& r0, uint32_t& r1, uint32_t& r2,
                                        uint32_t& r3, const void* p) {
    uint32_t a = (uint32_t)__cvta_generic_to_shared(p);
    asm volatile("ldmatrix.sync.aligned.m8n8.x4.shared.b16 {%0,%1,%2,%3},[%4];"
                 : "=r"(r0), "=r"(r1), "=r"(r2), "=r"(r3) : "r"(a));
}
__device__ __forceinline__ void ldsm_x4t(uint32_t& r0, uint32_t& r1, uint32_t& r2,
                                         uint32_t& r3, const void* p) {
    uint32_t a = (uint32_t)__cvta_generic_to_shared(p);
    asm volatile("ldmatrix.sync.aligned.m8n8.x4.trans.shared.b16 {%0,%1,%2,%3},[%4];"
                 : "=r"(r0), "=r"(r1), "=r"(r2), "=r"(r3) : "r"(a));
}
__device__ __forceinline__ void mma_f16(float* c, const uint32_t* a, const uint32_t* b) {
    asm volatile("mma.sync.aligned.m16n8k16.row.col.f32.f16.f16.f32 "
        "{%0,%1,%2,%3},{%4,%5,%6,%7},{%8,%9},{%0,%1,%2,%3};"
        : "+f"(c[0]), "+f"(c[1]), "+f"(c[2]), "+f"(c[3])
        : "r"(a[0]), "r"(a[1]), "r"(a[2]), "r"(a[3]), "r"(b[0]), "r"(b[1]));
}

__global__ __launch_bounds__(256) void k_gemm_f16(
    const __half* __restrict__ A, const __half* __restrict__ B,
    const float* __restrict__ bias, float* __restrict__ C,
    int M, int Nn, int K)
{
    __shared__ __half As[2][128][40];
    __shared__ __half Bs[2][32][136];
    int tid = threadIdx.x;
    int lane = tid & 31, warp = tid >> 5;
    int row0 = blockIdx.y * 128, col0 = blockIdx.x * 128;
    int mbase = (warp & 1) * 64, nbase = (warp >> 1) * 32;

    float acc[4][4][4] = {};
    int KT = K / 32;

    // stage loader
    #define LOAD_STAGE(st, kt) do {                                            \
        _Pragma("unroll")                                                       \
        for (int p = 0; p < 2; p++) {                                           \
            int c  = tid + p*256;                                               \
            int ar = c >> 2, akc = (c & 3) * 8;                                 \
            bool pr = (row0 + ar) < M;                                          \
            cp_async16(&As[st][ar][akc],                                        \
                       A + (long)(row0 + ar)*K + (kt)*32 + akc, pr);            \
            int brr = c >> 4, bnc = (c & 15) * 8;                               \
            cp_async16(&Bs[st][brr][bnc],                                       \
                       B + (long)((kt)*32 + brr)*Nn + col0 + bnc, true);        \
        }                                                                       \
        asm volatile("cp.async.commit_group;");                                 \
    } while (0)

    LOAD_STAGE(0, 0);

    for (int kt = 0; kt < KT; kt++) {
        int cur = kt & 1;
        if (kt + 1 < KT) {
            LOAD_STAGE(cur ^ 1, kt + 1);
            asm volatile("cp.async.wait_group 1;");
        } else {
            asm volatile("cp.async.wait_group 0;");
        }
        __syncthreads();

        #pragma unroll
        for (int ks = 0; ks < 2; ks++) {
            uint32_t a[4][4], b[4][2];
            #pragma unroll
            for (int mt = 0; mt < 4; mt++) {
                ldsm_x4(a[mt][0], a[mt][1], a[mt][2], a[mt][3],
                        &As[cur][mbase + mt*16 + (lane & 15)][ks*16 + (lane >> 4)*8]);
            }
            #pragma unroll
            for (int np = 0; np < 2; np++) {
                ldsm_x4t(b[np*2][0], b[np*2][1], b[np*2+1][0], b[np*2+1][1],
                         &Bs[cur][ks*16 + (lane & 15)][nbase + np*16 + (lane >> 4)*8]);
            }
            #pragma unroll
            for (int mt = 0; mt < 4; mt++)
                #pragma unroll
                for (int nt = 0; nt < 4; nt++)
                    mma_f16(acc[mt][nt], a[mt], b[nt]);
        }
        __syncthreads();
    }
    #undef LOAD_STAGE

    #pragma unroll
    for (int mt = 0; mt < 4; mt++) {
        int r0 = row0 + mbase + mt*16 + (lane >> 2);
        #pragma unroll
        for (int nt = 0; nt < 4; nt++) {
            int cn = col0 + nbase + nt*8 + (lane & 3)*2;
            float b0 = bias ? bias[cn]   : 0.f;
            float b1 = bias ? bias[cn+1] : 0.f;
            if (r0 < M) {
                C[(long)r0*Nn + cn]     = acc[mt][nt][0] + b0;
                C[(long)r0*Nn + cn + 1] = acc[mt][nt][1] + b1;
            }
            if (r0 + 8 < M) {
                C[(long)(r0+8)*Nn + cn]     = acc[mt][nt][2] + b0;
                C[(long)(r0+8)*Nn + cn + 1] = acc[mt][nt][3] + b1;
            }
        }
    }
}

// ---------------- weight prep --------------------------------------------------------
__global__ void k_f2h(const float* __restrict__ src, __half* __restrict__ dst, long n) {
    long i = blockIdx.x * (long)blockDim.x + threadIdx.x;
    if (i < n) dst[i] = __float2half(src[i]);
}
__global__ void k_prep_wc(const float* __restrict__ Wc) {  // [L][512][192] -> [L][512][256]
    long i = blockIdx.x * (long)blockDim.x + threadIdx.x;
    long tot = (long)LAYERS * HID * COMBP;
    if (i >= tot) return;
    int c = (int)(i & 255);
    long rl = i >> 8;               // l*512 + r
    d_wc16[i] = (c < COMBC) ? __float2half(Wc[rl*COMBC + c]) : __half(0.f);
}
__global__ void k_prep_bc(const float* __restrict__ bc) {  // [L][192] -> [L][256]
    int i = blockIdx.x * blockDim.x + threadIdx.x;
    if (i >= LAYERS*COMBP) return;
    int c = i & 255, l = i >> 8;
    d_bcp[i] = (c < COMBC) ? bc[l*COMBC + c] : 0.f;
}

// ---------------- column stats (deterministic two pass) ---------------------------
__global__ void k_colstats_partial(const float* __restrict__ X, int M, int C, int chunks,
                                   float* __restrict__ part) {
    int c = threadIdx.x;
    int ch = blockIdx.x;
    int rpc = (M + chunks - 1) / chunks;
    int r0 = ch * rpc, r1 = min(M, r0 + rpc);
    float s = 0.f, ss = 0.f;
    for (int r = r0; r < r1; r++) {
        float v = X[(long)r*C + c];
        s += v; ss += v*v;
    }
    part[(long)ch*2*C + c]     = s;
    part[(long)ch*2*C + C + c] = ss;
}
__global__ void k_colstats_final(const float* __restrict__ part, int chunks, int C, int M,
                                 const float* __restrict__ g, const float* __restrict__ b,
                                 float* __restrict__ scale, float* __restrict__ shift) {
    int c = blockIdx.x * blockDim.x + threadIdx.x;
    if (c >= C) return;
    float s = 0.f, ss = 0.f;
    for (int ch = 0; ch < chunks; ch++) {
        s  += part[(long)ch*2*C + c];
        ss += part[(long)ch*2*C + C + c];
    }
    float mean = s / (float)M;
    float var  = ss / (float)M - mean*mean;
    float sc   = g[c] * rsqrtf(var + EPSBN);
    scale[c] = sc;
    shift[c] = b[c] - mean*sc;
}

// ---------------- bn+relu apply, float4, optional fp16 sidecar ----------------------
__global__ void k_bn4(const float4* __restrict__ X, const float* __restrict__ scale,
                      const float* __restrict__ shift, float4* __restrict__ out,
                      __half2* __restrict__ outh, int total4, int c4mask, int residual) {
    int i = blockIdx.x * blockDim.x + threadIdx.x;
    if (i >= total4) return;
    int c = (i & c4mask) * 4;
    float4 v = X[i];
    float4 r;
    r.x = fmaxf(fmaf(v.x, scale[c+0], shift[c+0]), 0.f);
    r.y = fmaxf(fmaf(v.y, scale[c+1], shift[c+1]), 0.f);
    r.z = fmaxf(fmaf(v.z, scale[c+2], shift[c+2]), 0.f);
    r.w = fmaxf(fmaf(v.w, scale[c+3], shift[c+3]), 0.f);
    if (residual) {
        float4 h = out[i];
        r.x += h.x; r.y += h.y; r.z += h.z; r.w += h.w;
    }
    out[i] = r;
    if (outh) {
        outh[i*2]   = __floats2half2_rn(r.x, r.y);
        outh[i*2+1] = __floats2half2_rn(r.z, r.w);
    }
}

// ---------------- CSR build --------------------------------------------------------
__global__ void k_csr_zero() {
    int i = blockIdx.x * blockDim.x + threadIdx.x;
    if (i < NN) { d_deg[i] = 0; d_cur[i] = 0; }
}
__global__ void k_csr_count(const int* __restrict__ edst) {
    int e = blockIdx.x * blockDim.x + threadIdx.x;
    if (e < EE) atomicAdd(&d_deg[edst[e]], 1);
}
#define SCB 200
#define SCCHUNK 500
__global__ void k_scan_part() {
    int b = blockIdx.x, t = threadIdx.x;
    int beg = b * SCCHUNK, endn = min(beg + SCCHUNK, NN);
    int s = 0;
    for (int i = beg + t; i < endn; i += 128) s += d_deg[i];
    __shared__ int sh[128];
    sh[t] = s; __syncthreads();
    for (int o = 64; o; o >>= 1) { if (t < o) sh[t] += sh[t+o]; __syncthreads(); }
    if (!t) d_bsum[b] = sh[0];
}
__global__ void k_scan_mid() {
    int run = 0;
    for (int i = 0; i < SCB; i++) { int v = d_bsum[i]; d_bsum[i] = run; run += v; }
}
__global__ void k_scan_write() {
    int b = blockIdx.x;
    int run = d_bsum[b];
    int beg = b * SCCHUNK, endn = min(beg + SCCHUNK, NN);
    for (int i = beg; i < endn; i++) { d_off[i] = run; run += d_deg[i]; }
    if (b == SCB - 1) d_off[NN] = run;
}
__global__ void k_csr_fill(const int* __restrict__ esrc, const int* __restrict__ edst) {
    int e = blockIdx.x * blockDim.x + threadIdx.x;
    if (e >= EE) return;
    int d = edst[e];
    int p = d_off[d] + atomicAdd(&d_cur[d], 1);
    d_csrc[p] = esrc[e];
}

// ---------------- fused aggregation + head-combine einsum --------------------------
__global__ __launch_bounds__(128) void k_agg(const float* __restrict__ bases,
                                             const float* __restrict__ comb,
                                             float* __restrict__ out) {
    int n = blockIdx.x;
    int tid = threadIdx.x;       // 128, each owns 4 contiguous cols
    __shared__ float s_s[HID], s_m[HID], s_c[COMBC];
    __shared__ int   s_idx[128];

    int q = tid * 4;
    const float4* brow = (const float4*)&bases[(long)n*HID];
    float4 sv = brow[tid];       // self message
    float4 mv = sv;

    int beg = d_off[n], endp = d_off[n+1];
    for (int base = beg; base < endp; base += 128) {
        int m = min(128, endp - base);
        if (tid < m) s_idx[tid] = d_csrc[base + tid];
        __syncthreads();
        for (int j = 0; j < m; j++) {
            const float4 v = ((const float4*)&bases[(long)s_idx[j]*HID])[tid];
            sv.x += v.x; sv.y += v.y; sv.z += v.z; sv.w += v.w;
            mv.x = fmaxf(mv.x, v.x); mv.y = fmaxf(mv.y, v.y);
            mv.z = fmaxf(mv.z, v.z); mv.w = fmaxf(mv.w, v.w);
        }
        __syncthreads();
    }

    ((float4*)s_s)[tid] = sv;
    ((float4*)s_m)[tid] = mv;
    if (tid < COMBC/4) ((float4*)s_c)[tid] = ((const float4*)&comb[(long)n*COMBP])[tid];
    __syncthreads();

    float invc = 1.f / (float)(endp - beg + 1);
    int h = q >> 6;
    const float* w = &s_c[h * (NAGG*BASES)];
    float o[4] = {0.f, 0.f, 0.f, 0.f};
    #pragma unroll
    for (int b = 0; b < BASES; b++) {
        float ws = w[b];
        float wm = w[8 + b];
        float wx = w[16 + b];
        #pragma unroll
        for (int j = 0; j < 4; j++) {
            int f = (q + j) & 63;
            float s = s_s[b*FH + f];
            float x = s_m[b*FH + f];
            o[j] += ws * s + wm * s * invc + wx * x;
        }
    }
    float4 r; r.x = o[0]; r.y = o[1]; r.z = o[2]; r.w = o[3];
    ((float4*)&out[(long)n*HID])[tid] = r;
}

// ---------------- graph mean pool (batch sorted) -----------------------------------
__global__ __launch_bounds__(512) void k_pool(const float* __restrict__ h,
                                              const int* __restrict__ batch) {
    int g = blockIdx.x;
    int tid = threadIdx.x;
    int lo = 0, hi = NN;
    while (lo < hi) { int mid = (lo + hi) >> 1; if (batch[mid] < g) lo = mid + 1; else hi = mid; }
    int start = lo;
    hi = NN;
    while (lo < hi) { int mid = (lo + hi) >> 1; if (batch[mid] < g + 1) lo = mid + 1; else hi = mid; }
    int end = lo;
    float acc = 0.f;
    for (int i = start; i < end; i++) acc += h[(long)i*HID + tid];
    int c = end - start;
    d_pool[(long)g*HID + tid] = acc / (float)max(c, 1);
}

// ---------------- concat + final head ----------------------------------------------
__global__ void k_concat(const float* __restrict__ z, const float* __restrict__ desc) {
    int i = blockIdx.x * blockDim.x + threadIdx.x;
    if (i >= GG*CAT) return;
    int g = i / CAT, c = i % CAT;
    d_zc[i] = (c < 128) ? z[g*128 + c] : desc[g*DESC + (c - 128)];
}
__global__ void k_final(const float* __restrict__ z, const float* __restrict__ W,
                        const float* __restrict__ b, float* __restrict__ out) {
    int g = blockIdx.x * 8 + (threadIdx.x >> 5);
    int lane = threadIdx.x & 31;
    if (g >= GG) return;
    float acc = 0.f;
    #pragma unroll
    for (int k = lane; k < 128; k += 32) acc += z[g*128 + k] * W[k];
    #pragma unroll
    for (int o = 16; o; o >>= 1) acc += __shfl_down_sync(0xffffffffu, acc, o);
    if (lane == 0) out[g] = acc + b[0];
}

// ---------------- host orchestration ------------------------------------------------
static inline void* sym(const void* s) { void* p = nullptr; cudaGetSymbolAddress(&p, s); return p; }

extern "C" void kernel_launch(void* const* d_in, const int* in_sizes, int n_in,
                              void* d_out, int out_size) {
    const float* x       = (const float*)d_in[0];
    const int*   ei      = (const int*)  d_in[1];
    const int*   batch   = (const int*)  d_in[2];
    const float* desc    = (const float*)d_in[3];
    const float* lin1_W  = (const float*)d_in[4];
    const float* norm1_g = (const float*)d_in[6];
    const float* norm1_b = (const float*)d_in[7];
    const float* Wb_all  = (const float*)d_in[8];
    const float* Wc_all  = (const float*)d_in[9];
    const float* bc_all  = (const float*)d_in[10];
    const float* ng_all  = (const float*)d_in[12];
    const float* nb_all  = (const float*)d_in[13];
    const float* mlp_W1  = (const float*)d_in[14];
    const float* mlp_g1  = (const float*)d_in[15];
    const float* mlp_b1  = (const float*)d_in[16];
    const float* mlp_W2  = (const float*)d_in[17];
    const float* mlp_g2  = (const float*)d_in[18];
    const float* mlp_b2  = (const float*)d_in[19];
    const float* lin2_W  = (const float*)d_in[20];
    const float* bn2_g   = (const float*)d_in[22];
    const float* bn2_b   = (const float*)d_in[23];
    const float* out_W   = (const float*)d_in[24];
    const float* out_b   = (const float*)d_in[25];
    float* out = (float*)d_out;

    const int* esrc = ei;
    const int* edst = ei + EE;

    float*  p_h     = (float*) sym(d_h);
    __half* p_hh    = (__half*)sym(d_hh);
    float*  p_t     = (float*) sym(d_t);
    float*  p_bases = (float*) sym(d_bases);
    float*  p_comb  = (float*) sym(d_comb);
    float*  p_part  = (float*) sym(d_part);
    float*  p_scale = (float*) sym(d_scale);
    float*  p_shift = (float*) sym(d_shift);
    float*  p_pool  = (float*) sym(d_pool);
    float*  p_z1    = (float*) sym(d_z1);
    float*  p_z2    = (float*) sym(d_z2);
    float*  p_zc    = (float*) sym(d_zc);
    float*  p_z3    = (float*) sym(d_z3);
    __half* p_wb16  = (__half*)sym(d_wb16);
    __half* p_wc16  = (__half*)sym(d_wc16);
    float*  p_bcp   = (float*) sym(d_bcp);

    const int NH4 = NN * (HID/4);

    // ---- weight prep (fp16 + padding) ----
    {
        long nwb = (long)LAYERS*HID*HID;
        k_f2h<<<(int)((nwb + 255)/256), 256>>>(Wb_all, p_wb16, nwb);
        long nwc = (long)LAYERS*HID*COMBP;
        k_prep_wc<<<(int)((nwc + 255)/256), 256>>>(Wc_all);
        k_prep_bc<<<(LAYERS*COMBP + 255)/256, 256>>>(bc_all);
    }

    // ---- CSR build ----
    k_csr_zero <<<(NN + 255)/256, 256>>>();
    k_csr_count<<<(EE + 255)/256, 256>>>(edst);
    k_scan_part<<<SCB, 128>>>();
    k_scan_mid <<<1, 1>>>();
    k_scan_write<<<SCB, 1>>>();
    k_csr_fill <<<(EE + 255)/256, 256>>>(esrc, edst);

    // ---- lin1 + BN + relu -> h (+fp16 copy) ----
    k_lin1<<<NN, 256>>>(x, lin1_W, p_t);
    k_colstats_partial<<<256, HID>>>(p_t, NN, HID, 256, p_part);
    k_colstats_final<<<2, 256>>>(p_part, 256, HID, NN, norm1_g, norm1_b, p_scale, p_shift);
    k_bn4<<<(NH4 + 255)/256, 256>>>((const float4*)p_t, p_scale, p_shift,
                                    (float4*)p_h, (__half2*)p_hh, NH4, (HID/4)-1, 0);

    // ---- EGConv layers ----
    dim3 grid_b(HID/128, (NN + 127)/128);
    dim3 grid_c(COMBP/128, (NN + 127)/128);

    for (int l = 0; l < LAYERS; l++) {
        const __half* Wb = p_wb16 + (long)l * HID * HID;
        const __half* Wc = p_wc16 + (long)l * HID * COMBP;
        const float*  bc = p_bcp + l * COMBP;
        const float*  ng = ng_all + (long)l * HID;
        const float*  nb = nb_all + (long)l * HID;

        k_gemm_f16<<<grid_b, 256>>>(p_hh, Wb, nullptr, p_bases, NN, HID, HID);
        k_gemm_f16<<<grid_c, 256>>>(p_hh, Wc, bc, p_comb, NN, COMBP, HID);
        k_agg<<<NN, 128>>>(p_bases, p_comb, p_t);
        k_colstats_partial<<<256, HID>>>(p_t, NN, HID, 256, p_part);
        k_colstats_final<<<2, 256>>>(p_part, 256, HID, NN, ng, nb, p_scale, p_shift);
        k_bn4<<<(NH4 + 255)/256, 256>>>((const float4*)p_t, p_scale, p_shift,
                                        (float4*)p_h, (__half2*)p_hh, NH4, (HID/4)-1, 1);
    }

    // ---- pool ----
    k_pool<<<GG, HID>>>(p_h, batch);

    // ---- MLP head ----
    dim3 g1((256 + BN - 1)/BN, (GG + BM - 1)/BM);
    k_gemm<<<g1, 256>>>(p_pool, mlp_W1, nullptr, p_z1, GG, 256, HID);
    k_colstats_partial<<<64, 256>>>(p_z1, GG, 256, 64, p_part);
    k_colstats_final<<<1, 256>>>(p_part, 64, 256, GG, mlp_g1, mlp_b1, p_scale, p_shift);
    k_bn4<<<(GG*64 + 255)/256, 256>>>((const float4*)p_z1, p_scale, p_shift,
                                      (float4*)p_z1, nullptr, GG*64, 63, 0);

    dim3 g2((128 + BN - 1)/BN, (GG + BM - 1)/BM);
    k_gemm<<<g2, 256>>>(p_z1, mlp_W2, nullptr, p_z2, GG, 128, 256);
    k_colstats_partial<<<64, 128>>>(p_z2, GG, 128, 64, p_part);
    k_colstats_final<<<1, 128>>>(p_part, 64, 128, GG, mlp_g2, mlp_b2, p_scale, p_shift);
    k_bn4<<<(GG*32 + 255)/256, 256>>>((const float4*)p_z2, p_scale, p_shift,
                                      (float4*)p_z2, nullptr, GG*32, 31, 0);

    k_concat<<<(GG*CAT + 255)/256, 256>>>(p_z2, desc);

    dim3 g3((128 + BN - 1)/BN, (GG + BM - 1)/BM);
    k_gemm<<<g3, 256>>>(p_zc, lin2_W, nullptr, p_z3, GG, 128, CAT);
    k_colstats_partial<<<64, 128>>>(p_z3, GG, 128, 64, p_part);
    k_colstats_final<<<1, 128>>>(p_part, 64, 128, GG, bn2_g, bn2_b, p_scale, p_shift);
    k_bn4<<<(GG*32 + 255)/256, 256>>>((const float4*)p_z3, p_scale, p_shift,
                                      (float4*)p_z3, nullptr, GG*32, 31, 0);

    k_final<<<GG/8, 256>>>(p_z3, out_W, out_b, out);
}

// round 4
// speedup vs baseline: 5.9512x; 1.0021x over previous
#include <cuda_runtime.h>
#include <cuda_fp16.h>
#include <cstdint>

#define NN   100000
#define EE   200000
#define GG   4096
#define HID  512
#define LAYERS 4
#define HEADS 8
#define BASES 8
#define NAGG 3
#define FH   64
#define COMBC 192
#define COMBP 256
#define NCAT 768                   // 512 bases + 256 comb(padded)
#define DESC 200
#define CAT  (128 + DESC)          // 328
#define EPSBN 1e-5f

// fused GEMM smem: 3 stages, As[128][40] halves + Bs[32][264] halves
#define FG_AS_BYTES (3*128*40*2)
#define FG_BS_BYTES (3*32*264*2)
#define FG_SMEM (FG_AS_BYTES + FG_BS_BYTES)   // 81408

// ---------------- scratch (static device allocations; no cudaMalloc) ----------------
__device__ float  d_h     [(long)NN*HID];
__device__ __half d_hh    [(long)NN*HID];
__device__ float  d_t     [(long)NN*HID];
__device__ __half d_bases [(long)NN*HID];      // fp16 bases
__device__ float  d_comb  [(long)NN*COMBP];
__device__ float  d_part  [256*2*HID];
__device__ float  d_scale [HID];
__device__ float  d_shift [HID];
__device__ float  d_pool  [(long)GG*HID];
__device__ float  d_z1    [(long)GG*256];
__device__ float  d_z2    [(long)GG*128];
__device__ float  d_zc    [(long)GG*CAT];
__device__ float  d_z3    [(long)GG*128];
__device__ __half d_wcat  [(long)LAYERS*HID*NCAT];
__device__ float  d_bcp   [LAYERS*COMBP];
// CSR
__device__ int d_deg [NN];
__device__ int d_off [NN+1];
__device__ int d_cur [NN];
__device__ int d_csrc[EE];
__device__ int d_bsum[256];

// ---------------- lin1 -----------------------------------------------------------
__global__ void k_lin1(const float* __restrict__ x, const float* __restrict__ W,
                       float* __restrict__ out) {
    int n = blockIdx.x;
    __shared__ float xs[27];
    int tid = threadIdx.x;
    if (tid < 27) xs[tid] = x[n*27 + tid];
    __syncthreads();
    for (int c = tid; c < HID; c += blockDim.x) {
        float acc = 0.f;
        #pragma unroll
        for (int k = 0; k < 27; k++) acc += xs[k] * W[k*HID + c];
        out[(long)n*HID + c] = acc;
    }
}

// ---------------- fp32 tiled SGEMM (small head GEMMs) ------------------------------
#define BM 128
#define BN 128
#define BK 8
#define TM 8
#define TN 8
__global__ __launch_bounds__(256) void k_gemm(
    const float* __restrict__ A, const float* __restrict__ B,
    const float* __restrict__ bias, float* __restrict__ C,
    int M, int Nn, int K)
{
    __shared__ float As[BK][BM];
    __shared__ float Bs[BK][BN];
    int tid  = threadIdx.x;
    int row0 = blockIdx.y * BM;
    int col0 = blockIdx.x * BN;
    int tr = tid / 16, tc = tid % 16;
    float acc[TM][TN] = {};
    for (int kt = 0; kt < K; kt += BK) {
        #pragma unroll
        for (int i = 0; i < 4; i++) {
            int idx = tid + i*256;
            int m = idx >> 3, k = idx & 7;
            int gm = row0 + m, gk = kt + k;
            As[k][m] = (gm < M && gk < K) ? A[(long)gm*K + gk] : 0.f;
        }
        #pragma unroll
        for (int i = 0; i < 4; i++) {
            int idx = tid + i*256;
            int k = idx >> 7, n = idx & 127;
            int gk = kt + k, gn = col0 + n;
            Bs[k][n] = (gk < K && gn < Nn) ? B[(long)gk*Nn + gn] : 0.f;
        }
        __syncthreads();
        #pragma unroll
        for (int k = 0; k < BK; k++) {
            float a[TM], b[TN];
            #pragma unroll
            for (int i = 0; i < TM; i++) a[i] = As[k][tr*TM + i];
            #pragma unroll
            for (int j = 0; j < TN; j++) b[j] = Bs[k][tc*TN + j];
            #pragma unroll
            for (int i = 0; i < TM; i++)
                #pragma unroll
                for (int j = 0; j < TN; j++)
                    acc[i][j] += a[i] * b[j];
        }
        __syncthreads();
    }
    #pragma unroll
    for (int i = 0; i < TM; i++) {
        int gm = row0 + tr*TM + i;
        if (gm >= M) continue;
        #pragma unroll
        for (int j = 0; j < TN; j++) {
            int gn = col0 + tc*TN + j;
            if (gn < Nn) C[(long)gm*Nn + gn] = acc[i][j] + (bias ? bias[gn] : 0.f);
        }
    }
}

// ---------------- fused fp16 tensor-core GEMM (N=768, K=512 fixed) ------------------
// A[Mx512] f16, W[512x768] f16 -> cols [0,512) as f16 into bases, cols [512,768)
// +bias as f32 into comb. Tile 128x256x32, 8 warps (2Mx4N), warp tile 64x64,
// 3-stage cp.async, mma.m16n8k16 via ldmatrix.
__device__ __forceinline__ void cp_async16(void* smem, const void* gmem, bool pred) {
    unsigned sa = (unsigned)__cvta_generic_to_shared(smem);
    int sz = pred ? 16 : 0;
    asm volatile("cp.async.cg.shared.global [%0], [%1], 16, %2;"
                 :: "r"(sa), "l"(gmem), "r"(sz));
}
__device__ __forceinline__ void ldsm_x4(uint32_t& r0, uint32_t& r1, uint32_t& r2,
                                        uint32_t& r3, const void* p) {
    uint32_t a = (uint32_t)__cvta_generic_to_shared(p);
    asm volatile("ldmatrix.sync.aligned.m8n8.x4.shared.b16 {%0,%1,%2,%3},[%4];"
                 : "=r"(r0), "=r"(r1), "=r"(r2), "=r"(r3) : "r"(a));
}
__device__ __forceinline__ void ldsm_x4t(uint32_t& r0, uint32_t& r1, uint32_t& r2,
                                         uint32_t& r3, const void* p) {
    uint32_t a = (uint32_t)__cvta_generic_to_shared(p);
    asm volatile("ldmatrix.sync.aligned.m8n8.x4.trans.shared.b16 {%0,%1,%2,%3},[%4];"
                 : "=r"(r0), "=r"(r1), "=r"(r2), "=r"(r3) : "r"(a));
}
__device__ __forceinline__ void mma_f16(float* c, const uint32_t* a, const uint32_t* b) {
    asm volatile("mma.sync.aligned.m16n8k16.row.col.f32.f16.f16.f32 "
        "{%0,%1,%2,%3},{%4,%5,%6,%7},{%8,%9},{%0,%1,%2,%3};"
        : "+f"(c[0]), "+f"(c[1]), "+f"(c[2]), "+f"(c[3])
        : "r"(a[0]), "r"(a[1]), "r"(a[2]), "r"(a[3]), "r"(b[0]), "r"(b[1]));
}

typedef __half (*AsT)[128][40];
typedef __half (*BsT)[32][264];

__global__ __launch_bounds__(256, 1) void k_gemm_fused(
    const __half* __restrict__ A, const __half* __restrict__ W,
    const float* __restrict__ bias,
    __half* __restrict__ basesO, float* __restrict__ combO, int M)
{
    extern __shared__ __align__(16) char smraw[];
    AsT As = (AsT)smraw;
    BsT Bs = (BsT)(smraw + FG_AS_BYTES);

    int tid = threadIdx.x;
    int lane = tid & 31, warp = tid >> 5;
    int row0 = blockIdx.y * 128, col0 = blockIdx.x * 256;
    int mbase = (warp & 1) * 64, nbase = (warp >> 1) * 64;

    float acc[4][8][4] = {};
    const int KT = 16;   // 512/32

    #define LOADF(st, kt) do {                                                   \
        _Pragma("unroll")                                                         \
        for (int p = 0; p < 2; p++) {                                             \
            int c = tid + p*256;                                                  \
            int ar = c >> 2, akc = (c & 3) * 8;                                   \
            cp_async16(&As[st][ar][akc],                                          \
                       A + (long)(row0 + ar)*HID + (kt)*32 + akc,                 \
                       (row0 + ar) < M);                                          \
        }                                                                         \
        _Pragma("unroll")                                                         \
        for (int p = 0; p < 4; p++) {                                             \
            int c = tid + p*256;                                                  \
            int brr = c >> 5, bnc = (c & 31) * 8;                                 \
            cp_async16(&Bs[st][brr][bnc],                                         \
                       W + (long)((kt)*32 + brr)*NCAT + col0 + bnc, true);        \
        }                                                                         \
        asm volatile("cp.async.commit_group;");                                   \
    } while (0)

    LOADF(0, 0);
    LOADF(1, 1);

    for (int kt = 0; kt < KT; kt++) {
        int cur = kt % 3;
        if (kt >= KT - 1) asm volatile("cp.async.wait_group 0;");
        else              asm volatile("cp.async.wait_group 1;");
        __syncthreads();

        #pragma unroll
        for (int ks = 0; ks < 2; ks++) {
            uint32_t a[4][4], b[8][2];
            #pragma unroll
            for (int mt = 0; mt < 4; mt++)
                ldsm_x4(a[mt][0], a[mt][1], a[mt][2], a[mt][3],
                        &As[cur][mbase + mt*16 + (lane & 15)][ks*16 + (lane >> 4)*8]);
            #pragma unroll
            for (int np = 0; np < 4; np++)
                ldsm_x4t(b[np*2][0], b[np*2][1], b[np*2+1][0], b[np*2+1][1],
                         &Bs[cur][ks*16 + (lane & 15)][nbase + np*16 + (lane >> 4)*8]);
            #pragma unroll
            for (int mt = 0; mt < 4; mt++)
                #pragma unroll
                for (int nt = 0; nt < 8; nt++)
                    mma_f16(acc[mt][nt], a[mt], b[nt]);
        }
        __syncthreads();

        if (kt + 2 < KT) LOADF((kt + 2) % 3, kt + 2);
    }
    #undef LOADF

    // epilogue: blockIdx.x 0,1 -> bases fp16; blockIdx.x 2 -> comb fp32 + bias
    if (blockIdx.x < 2) {
        #pragma unroll
        for (int mt = 0; mt < 4; mt++) {
            int r0 = row0 + mbase + mt*16 + (lane >> 2);
            #pragma unroll
            for (int nt = 0; nt < 8; nt++) {
                int cn = col0 + nbase + nt*8 + (lane & 3)*2;
                if (r0 < M)
                    *(__half2*)&basesO[(long)r0*HID + cn] =
                        __floats2half2_rn(acc[mt][nt][0], acc[mt][nt][1]);
                if (r0 + 8 < M)
                    *(__half2*)&basesO[(long)(r0+8)*HID + cn] =
                        __floats2half2_rn(acc[mt][nt][2], acc[mt][nt][3]);
            }
        }
    } else {
        #pragma unroll
        for (int mt = 0; mt < 4; mt++) {
            int r0 = row0 + mbase + mt*16 + (lane >> 2);
            #pragma unroll
            for (int nt = 0; nt < 8; nt++) {
                int cc = nbase + nt*8 + (lane & 3)*2;   // 0..255
                float b0 = bias[cc], b1 = bias[cc+1];
                if (r0 < M) {
                    combO[(long)r0*COMBP + cc]     = acc[mt][nt][0] + b0;
                    combO[(long)r0*COMBP + cc + 1] = acc[mt][nt][1] + b1;
                }
                if (r0 + 8 < M) {
                    combO[(long)(r0+8)*COMBP + cc]     = acc[mt][nt][2] + b0;
                    combO[(long)(r0+8)*COMBP + cc + 1] = acc[mt][nt][3] + b1;
                }
            }
        }
    }
}

// ---------------- weight prep --------------------------------------------------------
__global__ void k_prep_wcat(const float* __restrict__ Wb, const float* __restrict__ Wc) {
    long i = blockIdx.x * (long)blockDim.x + threadIdx.x;
    long tot = (long)LAYERS * HID * NCAT;
    if (i >= tot) return;
    int c = (int)(i % NCAT);
    long rl = i / NCAT;                 // l*512 + k
    float v;
    if (c < HID)            v = Wb[rl*HID + c];
    else if (c < HID+COMBC) v = Wc[rl*COMBC + (c - HID)];
    else                    v = 0.f;
    d_wcat[i] = __float2half(v);
}
__global__ void k_prep_bc(const float* __restrict__ bc) {
    int i = blockIdx.x * blockDim.x + threadIdx.x;
    if (i >= LAYERS*COMBP) return;
    int c = i & 255, l = i >> 8;
    d_bcp[i] = (c < COMBC) ? bc[l*COMBC + c] : 0.f;
}

// ---------------- column stats (deterministic two pass) ---------------------------
__global__ void k_colstats_partial(const float* __restrict__ X, int M, int C, int chunks,
                                   float* __restrict__ part) {
    int c = threadIdx.x;
    int ch = blockIdx.x;
    int rpc = (M + chunks - 1) / chunks;
    int r0 = ch * rpc, r1 = min(M, r0 + rpc);
    float s = 0.f, ss = 0.f;
    for (int r = r0; r < r1; r++) {
        float v = X[(long)r*C + c];
        s += v; ss += v*v;
    }
    part[(long)ch*2*C + c]     = s;
    part[(long)ch*2*C + C + c] = ss;
}
__global__ void k_colstats_final(const float* __restrict__ part, int chunks, int C, int M,
                                 const float* __restrict__ g, const float* __restrict__ b,
                                 float* __restrict__ scale, float* __restrict__ shift) {
    int c = blockIdx.x * blockDim.x + threadIdx.x;
    if (c >= C) return;
    float s = 0.f, ss = 0.f;
    for (int ch = 0; ch < chunks; ch++) {
        s  += part[(long)ch*2*C + c];
        ss += part[(long)ch*2*C + C + c];
    }
    float mean = s / (float)M;
    float var  = ss / (float)M - mean*mean;
    float sc   = g[c] * rsqrtf(var + EPSBN);
    scale[c] = sc;
    shift[c] = b[c] - mean*sc;
}

// ---------------- bn+relu apply, float4, optional fp16 sidecar ----------------------
__global__ void k_bn4(const float4* __restrict__ X, const float* __restrict__ scale,
                      const float* __restrict__ shift, float4* __restrict__ out,
                      __half2* __restrict__ outh, int total4, int c4mask, int residual) {
    int i = blockIdx.x * blockDim.x + threadIdx.x;
    if (i >= total4) return;
    int c = (i & c4mask) * 4;
    float4 v = X[i];
    float4 r;
    r.x = fmaxf(fmaf(v.x, scale[c+0], shift[c+0]), 0.f);
    r.y = fmaxf(fmaf(v.y, scale[c+1], shift[c+1]), 0.f);
    r.z = fmaxf(fmaf(v.z, scale[c+2], shift[c+2]), 0.f);
    r.w = fmaxf(fmaf(v.w, scale[c+3], shift[c+3]), 0.f);
    if (residual) {
        float4 h = out[i];
        r.x += h.x; r.y += h.y; r.z += h.z; r.w += h.w;
    }
    out[i] = r;
    if (outh) {
        outh[i*2]   = __floats2half2_rn(r.x, r.y);
        outh[i*2+1] = __floats2half2_rn(r.z, r.w);
    }
}

// ---------------- CSR build --------------------------------------------------------
__global__ void k_csr_zero() {
    int i = blockIdx.x * blockDim.x + threadIdx.x;
    if (i < NN) { d_deg[i] = 0; d_cur[i] = 0; }
}
__global__ void k_csr_count(const int* __restrict__ edst) {
    int e = blockIdx.x * blockDim.x + threadIdx.x;
    if (e < EE) atomicAdd(&d_deg[edst[e]], 1);
}
#define SCB 200
#define SCCHUNK 500
__global__ void k_scan_part() {
    int b = blockIdx.x, t = threadIdx.x;
    int beg = b * SCCHUNK, endn = min(beg + SCCHUNK, NN);
    int s = 0;
    for (int i = beg + t; i < endn; i += 128) s += d_deg[i];
    __shared__ int sh[128];
    sh[t] = s; __syncthreads();
    for (int o = 64; o; o >>= 1) { if (t < o) sh[t] += sh[t+o]; __syncthreads(); }
    if (!t) d_bsum[b] = sh[0];
}
__global__ void k_scan_mid() {
    int run = 0;
    for (int i = 0; i < SCB; i++) { int v = d_bsum[i]; d_bsum[i] = run; run += v; }
}
__global__ void k_scan_write() {
    int b = blockIdx.x;
    int run = d_bsum[b];
    int beg = b * SCCHUNK, endn = min(beg + SCCHUNK, NN);
    for (int i = beg; i < endn; i++) { d_off[i] = run; run += d_deg[i]; }
    if (b == SCB - 1) d_off[NN] = run;
}
__global__ void k_csr_fill(const int* __restrict__ esrc, const int* __restrict__ edst) {
    int e = blockIdx.x * blockDim.x + threadIdx.x;
    if (e >= EE) return;
    int d = edst[e];
    int p = d_off[d] + atomicAdd(&d_cur[d], 1);
    d_csrc[p] = esrc[e];
}

// ---------------- fused aggregation + head-combine einsum (fp16 gather) -------------
__global__ __launch_bounds__(128) void k_agg(const __half* __restrict__ bases,
                                             const float* __restrict__ comb,
                                             float* __restrict__ out) {
    int n = blockIdx.x;
    int tid = threadIdx.x;       // 128 threads, each owns 4 contiguous cols
    __shared__ float s_s[HID], s_m[HID], s_c[COMBC];
    __shared__ int   s_idx[128];

    int q = tid * 4;
    const uint2* brow = (const uint2*)&bases[(long)n*HID];
    uint2 sp = brow[tid];
    float2 p0 = __half22float2(*(__half2*)&sp.x);
    float2 p1 = __half22float2(*(__half2*)&sp.y);
    float4 sv = make_float4(p0.x, p0.y, p1.x, p1.y);
    float4 mv = sv;

    int beg = d_off[n], endp = d_off[n+1];
    for (int base = beg; base < endp; base += 128) {
        int m = min(128, endp - base);
        if (tid < m) s_idx[tid] = d_csrc[base + tid];
        __syncthreads();
        for (int j = 0; j < m; j++) {
            uint2 vp = ((const uint2*)&bases[(long)s_idx[j]*HID])[tid];
            float2 a = __half22float2(*(__half2*)&vp.x);
            float2 b = __half22float2(*(__half2*)&vp.y);
            sv.x += a.x; sv.y += a.y; sv.z += b.x; sv.w += b.y;
            mv.x = fmaxf(mv.x, a.x); mv.y = fmaxf(mv.y, a.y);
            mv.z = fmaxf(mv.z, b.x); mv.w = fmaxf(mv.w, b.y);
        }
        __syncthreads();
    }

    ((float4*)s_s)[tid] = sv;
    ((float4*)s_m)[tid] = mv;
    if (tid < COMBC/4) ((float4*)s_c)[tid] = ((const float4*)&comb[(long)n*COMBP])[tid];
    __syncthreads();

    float invc = 1.f / (float)(endp - beg + 1);
    int h = q >> 6;
    const float* w = &s_c[h * (NAGG*BASES)];
    float o[4] = {0.f, 0.f, 0.f, 0.f};
    #pragma unroll
    for (int b = 0; b < BASES; b++) {
        float ws = w[b];
        float wm = w[8 + b];
        float wx = w[16 + b];
        #pragma unroll
        for (int j = 0; j < 4; j++) {
            int f = (q + j) & 63;
            float s = s_s[b*FH + f];
            float x = s_m[b*FH + f];
            o[j] += ws * s + wm * s * invc + wx * x;
        }
    }
    float4 r; r.x = o[0]; r.y = o[1]; r.z = o[2]; r.w = o[3];
    ((float4*)&out[(long)n*HID])[tid] = r;
}

// ---------------- graph mean pool (batch sorted) -----------------------------------
__global__ __launch_bounds__(512) void k_pool(const float* __restrict__ h,
                                              const int* __restrict__ batch) {
    int g = blockIdx.x;
    int tid = threadIdx.x;
    int lo = 0, hi = NN;
    while (lo < hi) { int mid = (lo + hi) >> 1; if (batch[mid] < g) lo = mid + 1; else hi = mid; }
    int start = lo;
    hi = NN;
    while (lo < hi) { int mid = (lo + hi) >> 1; if (batch[mid] < g + 1) lo = mid + 1; else hi = mid; }
    int end = lo;
    float acc = 0.f;
    for (int i = start; i < end; i++) acc += h[(long)i*HID + tid];
    int c = end - start;
    d_pool[(long)g*HID + tid] = acc / (float)max(c, 1);
}

// ---------------- concat + final head ----------------------------------------------
__global__ void k_concat(const float* __restrict__ z, const float* __restrict__ desc) {
    int i = blockIdx.x * blockDim.x + threadIdx.x;
    if (i >= GG*CAT) return;
    int g = i / CAT, c = i % CAT;
    d_zc[i] = (c < 128) ? z[g*128 + c] : desc[g*DESC + (c - 128)];
}
__global__ void k_final(const float* __restrict__ z, const float* __restrict__ W,
                        const float* __restrict__ b, float* __restrict__ out) {
    int g = blockIdx.x * 8 + (threadIdx.x >> 5);
    int lane = threadIdx.x & 31;
    if (g >= GG) return;
    float acc = 0.f;
    #pragma unroll
    for (int k = lane; k < 128; k += 32) acc += z[g*128 + k] * W[k];
    #pragma unroll
    for (int o = 16; o; o >>= 1) acc += __shfl_down_sync(0xffffffffu, acc, o);
    if (lane == 0) out[g] = acc + b[0];
}

// ---------------- host orchestration ------------------------------------------------
static inline void* sym(const void* s) { void* p = nullptr; cudaGetSymbolAddress(&p, s); return p; }

extern "C" void kernel_launch(void* const* d_in, const int* in_sizes, int n_in,
                              void* d_out, int out_size) {
    const float* x       = (const float*)d_in[0];
    const int*   ei      = (const int*)  d_in[1];
    const int*   batch   = (const int*)  d_in[2];
    const float* desc    = (const float*)d_in[3];
    const float* lin1_W  = (const float*)d_in[4];
    const float* norm1_g = (const float*)d_in[6];
    const float* norm1_b = (const float*)d_in[7];
    const float* Wb_all  = (const float*)d_in[8];
    const float* Wc_all  = (const float*)d_in[9];
    const float* bc_all  = (const float*)d_in[10];
    const float* ng_all  = (const float*)d_in[12];
    const float* nb_all  = (const float*)d_in[13];
    const float* mlp_W1  = (const float*)d_in[14];
    const float* mlp_g1  = (const float*)d_in[15];
    const float* mlp_b1  = (const float*)d_in[16];
    const float* mlp_W2  = (const float*)d_in[17];
    const float* mlp_g2  = (const float*)d_in[18];
    const float* mlp_b2  = (const float*)d_in[19];
    const float* lin2_W  = (const float*)d_in[20];
    const float* bn2_g   = (const float*)d_in[22];
    const float* bn2_b   = (const float*)d_in[23];
    const float* out_W   = (const float*)d_in[24];
    const float* out_b   = (const float*)d_in[25];
    float* out = (float*)d_out;

    const int* esrc = ei;
    const int* edst = ei + EE;

    float*  p_h     = (float*) sym(d_h);
    __half* p_hh    = (__half*)sym(d_hh);
    float*  p_t     = (float*) sym(d_t);
    __half* p_bases = (__half*)sym(d_bases);
    float*  p_comb  = (float*) sym(d_comb);
    float*  p_part  = (float*) sym(d_part);
    float*  p_scale = (float*) sym(d_scale);
    float*  p_shift = (float*) sym(d_shift);
    float*  p_pool  = (float*) sym(d_pool);
    float*  p_z1    = (float*) sym(d_z1);
    float*  p_z2    = (float*) sym(d_z2);
    float*  p_zc    = (float*) sym(d_zc);
    float*  p_z3    = (float*) sym(d_z3);
    __half* p_wcat  = (__half*)sym(d_wcat);
    float*  p_bcp   = (float*) sym(d_bcp);

    const int NH4 = NN * (HID/4);

    static bool attr_done = false;
    if (!attr_done) {
        cudaFuncSetAttribute(k_gemm_fused,
                             cudaFuncAttributeMaxDynamicSharedMemorySize, FG_SMEM);
        attr_done = true;
    }

    // ---- weight prep (fp16 concat + padding) ----
    {
        long nw = (long)LAYERS*HID*NCAT;
        k_prep_wcat<<<(int)((nw + 255)/256), 256>>>(Wb_all, Wc_all);
        k_prep_bc<<<(LAYERS*COMBP + 255)/256, 256>>>(bc_all);
    }

    // ---- CSR build ----
    k_csr_zero <<<(NN + 255)/256, 256>>>();
    k_csr_count<<<(EE + 255)/256, 256>>>(edst);
    k_scan_part<<<SCB, 128>>>();
    k_scan_mid <<<1, 1>>>();
    k_scan_write<<<SCB, 1>>>();
    k_csr_fill <<<(EE + 255)/256, 256>>>(esrc, edst);

    // ---- lin1 + BN + relu -> h (+fp16 copy) ----
    k_lin1<<<NN, 256>>>(x, lin1_W, p_t);
    k_colstats_partial<<<256, HID>>>(p_t, NN, HID, 256, p_part);
    k_colstats_final<<<2, 256>>>(p_part, 256, HID, NN, norm1_g, norm1_b, p_scale, p_shift);
    k_bn4<<<(NH4 + 255)/256, 256>>>((const float4*)p_t, p_scale, p_shift,
                                    (float4*)p_h, (__half2*)p_hh, NH4, (HID/4)-1, 0);

    // ---- EGConv layers ----
    dim3 grid_f(3, (NN + 127)/128);

    for (int l = 0; l < LAYERS; l++) {
        const __half* Wl = p_wcat + (long)l * HID * NCAT;
        const float*  bc = p_bcp + l * COMBP;
        const float*  ng = ng_all + (long)l * HID;
        const float*  nb = nb_all + (long)l * HID;
        bool last = (l == LAYERS - 1);

        k_gemm_fused<<<grid_f, 256, FG_SMEM>>>(p_hh, Wl, bc, p_bases, p_comb, NN);
        k_agg<<<NN, 128>>>(p_bases, p_comb, p_t);
        k_colstats_partial<<<256, HID>>>(p_t, NN, HID, 256, p_part);
        k_colstats_final<<<2, 256>>>(p_part, 256, HID, NN, ng, nb, p_scale, p_shift);
        k_bn4<<<(NH4 + 255)/256, 256>>>((const float4*)p_t, p_scale, p_shift,
                                        (float4*)p_h, last ? nullptr : (__half2*)p_hh,
                                        NH4, (HID/4)-1, 1);
    }

    // ---- pool ----
    k_pool<<<GG, HID>>>(p_h, batch);

    // ---- MLP head ----
    dim3 g1((256 + BN - 1)/BN, (GG + BM - 1)/BM);
    k_gemm<<<g1, 256>>>(p_pool, mlp_W1, nullptr, p_z1, GG, 256, HID);
    k_colstats_partial<<<64, 256>>>(p_z1, GG, 256, 64, p_part);
    k_colstats_final<<<1, 256>>>(p_part, 64, 256, GG, mlp_g1, mlp_b1, p_scale, p_shift);
    k_bn4<<<(GG*64 + 255)/256, 256>>>((const float4*)p_z1, p_scale, p_shift,
                                      (float4*)p_z1, nullptr, GG*64, 63, 0);

    dim3 g2((128 + BN - 1)/BN, (GG + BM - 1)/BM);
    k_gemm<<<g2, 256>>>(p_z1, mlp_W2, nullptr, p_z2, GG, 128, 256);
    k_colstats_partial<<<64, 128>>>(p_z2, GG, 128, 64, p_part);
    k_colstats_final<<<1, 128>>>(p_part, 64, 128, GG, mlp_g2, mlp_b2, p_scale, p_shift);
    k_bn4<<<(GG*32 + 255)/256, 256>>>((const float4*)p_z2, p_scale, p_shift,
                                      (float4*)p_z2, nullptr, GG*32, 31, 0);

    k_concat<<<(GG*CAT + 255)/256, 256>>>(p_z2, desc);

    dim3 g3((128 + BN - 1)/BN, (GG + BM - 1)/BM);
    k_gemm<<<g3, 256>>>(p_zc, lin2_W, nullptr, p_z3, GG, 128, CAT);
    k_colstats_partial<<<64, 128>>>(p_z3, GG, 128, 64, p_part);
    k_colstats_final<<<1, 128>>>(p_part, 64, 128, GG, bn2_g, bn2_b, p_scale, p_shift);
    k_bn4<<<(GG*32 + 255)/256, 256>>>((const float4*)p_z3, p_scale, p_shift,
                                      (float4*)p_z3, nullptr, GG*32, 31, 0);

    k_final<<<GG/8, 256>>>(p_z3, out_W, out_b, out);
}